// round 1
// baseline (speedup 1.0000x reference)
#include <cuda_runtime.h>

// BalanceCrossEntropyLoss: top-k negative-loss selection via packed histogram.
//
// Pass 1: elementwise loss; pos_sum/pos_cnt/neg_cnt reductions; negative losses
//         binned into a 2048-bin privatized shared histogram. Each bin is a
//         single u64: count in bits [42:64), fixed-point (2^20) loss sum in
//         bits [0:42). One shared atomicAdd per negative pixel.
// Pass 2: single block. Descending suffix scan over bins -> threshold bin,
//         exact sums for fully-selected bins, uniform-model partial for the
//         boundary bin (first-order exact). Resets scratch for graph replay.

#define NBINS 2048
#define HIST_MAX 5.0f
#define SUM_SHIFT 42
#define SUM_SCALE 1048576.0f   // 2^20
#define SUM_INV   (1.0 / 1048576.0)

__device__ unsigned long long g_bins[NBINS];
__device__ double       g_posSum;
__device__ unsigned int g_posCnt;
__device__ unsigned int g_negCnt;

__global__ __launch_bounds__(512)
void bce_pass1(const float* __restrict__ pred,
               const float* __restrict__ gt,
               const float* __restrict__ mask,
               int n)
{
    __shared__ unsigned long long s_bins[NBINS];
    for (int i = threadIdx.x; i < NBINS; i += blockDim.x) s_bins[i] = 0ULL;
    __syncthreads();

    float    posSum = 0.0f;
    unsigned posCnt = 0, negCnt = 0;
    const float invw = (float)NBINS / HIST_MAX;

    const int tid    = blockIdx.x * blockDim.x + threadIdx.x;
    const int stride = gridDim.x * blockDim.x;
    const int n4     = n >> 2;

    const float4* p4 = reinterpret_cast<const float4*>(pred);
    const float4* g4 = reinterpret_cast<const float4*>(gt);
    const float4* m4 = reinterpret_cast<const float4*>(mask);

    for (int i = tid; i < n4; i += stride) {
        float4 pp = p4[i];
        float4 gg = g4[i];
        float4 mm = m4[i];
        float pv[4] = {pp.x, pp.y, pp.z, pp.w};
        float gv[4] = {gg.x, gg.y, gg.z, gg.w};
        float mv[4] = {mm.x, mm.y, mm.z, mm.w};
#pragma unroll
        for (int j = 0; j < 4; j++) {
            if (mv[j] != 0.0f) {
                if (gv[j] != 0.0f) {
                    // positive: loss = min(-log(p), 100)
                    float l = fminf(-__logf(pv[j]), 100.0f);
                    posSum += l;
                    posCnt++;
                } else {
                    // negative: loss = min(-log(1-p), 100)
                    float l = fminf(-__logf(1.0f - pv[j]), 100.0f);
                    negCnt++;
                    int b = (int)(l * invw);
                    b = min(b, NBINS - 1);
                    unsigned long long pk =
                        (1ULL << SUM_SHIFT) +
                        (unsigned long long)(l * SUM_SCALE + 0.5f);
                    atomicAdd(&s_bins[b], pk);
                }
            }
        }
    }
    // scalar tail (n not divisible by 4 — dead for this shape, kept for safety)
    for (int i = (n4 << 2) + tid; i < n; i += stride) {
        float mvx = mask[i];
        if (mvx != 0.0f) {
            float pvx = pred[i];
            if (gt[i] != 0.0f) {
                float l = fminf(-__logf(pvx), 100.0f);
                posSum += l; posCnt++;
            } else {
                float l = fminf(-__logf(1.0f - pvx), 100.0f);
                negCnt++;
                int b = min((int)(l * invw), NBINS - 1);
                unsigned long long pk =
                    (1ULL << SUM_SHIFT) +
                    (unsigned long long)(l * SUM_SCALE + 0.5f);
                atomicAdd(&s_bins[b], pk);
            }
        }
    }

    __syncthreads();
    // flush privatized histogram
    for (int i = threadIdx.x; i < NBINS; i += blockDim.x) {
        unsigned long long v = s_bins[i];
        if (v) atomicAdd(&g_bins[i], v);
    }
    // warp-level reduce of scalars, one global atomic per warp
#pragma unroll
    for (int off = 16; off; off >>= 1) {
        posSum += __shfl_down_sync(0xffffffffu, posSum, off);
        posCnt += __shfl_down_sync(0xffffffffu, posCnt, off);
        negCnt += __shfl_down_sync(0xffffffffu, negCnt, off);
    }
    if ((threadIdx.x & 31) == 0) {
        atomicAdd(&g_posSum, (double)posSum);
        atomicAdd(&g_posCnt, posCnt);
        atomicAdd(&g_negCnt, negCnt);
    }
}

__global__ __launch_bounds__(1024)
void bce_pass2(float* __restrict__ out)
{
    __shared__ unsigned int s_scan[1024];
    __shared__ double       s_red[32];

    const int t = threadIdx.x;
    // thread t owns bins in DESCENDING loss order: b0 (higher), b1
    const int b0 = NBINS - 1 - 2 * t;
    const int b1 = b0 - 1;

    unsigned long long pk0 = g_bins[b0];
    unsigned long long pk1 = g_bins[b1];
    unsigned c0 = (unsigned)(pk0 >> SUM_SHIFT);
    unsigned c1 = (unsigned)(pk1 >> SUM_SHIFT);
    const unsigned long long SMASK = (1ULL << SUM_SHIFT) - 1ULL;
    double s0 = (double)(pk0 & SMASK) * SUM_INV;
    double s1 = (double)(pk1 & SMASK) * SUM_INV;

    unsigned posCnt = g_posCnt;
    unsigned negCnt = g_negCnt;
    double   posSum = g_posSum;
    __syncthreads();
    // reset scratch for next graph replay (deterministic per call)
    g_bins[b0] = 0ULL;
    g_bins[b1] = 0ULL;
    if (t == 0) { g_posSum = 0.0; g_posCnt = 0u; g_negCnt = 0u; }

    // k = min(floor(neg_total), floor(pos_count * 3.0)) — mirror fp32 semantics
    double kd = fmin((double)negCnt, (double)floorf((float)posCnt * 3.0f));
    unsigned long long k = (unsigned long long)kd;

    // inclusive scan over per-thread counts (descending-bin order)
    unsigned v = c0 + c1;
    s_scan[t] = v;
    __syncthreads();
#pragma unroll
    for (int off = 1; off < 1024; off <<= 1) {
        unsigned add = (t >= off) ? s_scan[t - off] : 0u;
        __syncthreads();
        s_scan[t] += add;
        __syncthreads();
    }
    unsigned long long cum = (unsigned long long)(s_scan[t] - v); // count in strictly-higher bins

    double acc = 0.0;
    const double w = (double)HIST_MAX / (double)NBINS;
    // bin b0 (higher values) first
    if (cum + c0 <= k) {
        acc += s0;
    } else if (cum < k && c0 > 0) {
        double rem = (double)(k - cum);
        double m   = s0 / (double)c0;
        // uniform within bin: top-rem sum = rem*m + (w*rem/2)*(1 - rem/cnt)
        acc += rem * m + 0.5 * w * rem * (1.0 - rem / (double)c0);
    }
    cum += c0;
    if (cum + c1 <= k) {
        acc += s1;
    } else if (cum < k && c1 > 0) {
        double rem = (double)(k - cum);
        double m   = s1 / (double)c1;
        acc += rem * m + 0.5 * w * rem * (1.0 - rem / (double)c1);
    }

    // block reduce acc
#pragma unroll
    for (int off = 16; off; off >>= 1)
        acc += __shfl_down_sync(0xffffffffu, acc, off);
    if ((t & 31) == 0) s_red[t >> 5] = acc;
    __syncthreads();
    if (t < 32) {
        double a = s_red[t];
#pragma unroll
        for (int off = 16; off; off >>= 1)
            a += __shfl_down_sync(0xffffffffu, a, off);
        if (t == 0) {
            double denom = (double)posCnt + kd + 1e-6;
            out[0] = (float)((posSum + a) / denom);
        }
    }
}

extern "C" void kernel_launch(void* const* d_in, const int* in_sizes, int n_in,
                              void* d_out, int out_size)
{
    const float* pred = (const float*)d_in[0];
    const float* gt   = (const float*)d_in[1];
    const float* mask = (const float*)d_in[2];
    int n = in_sizes[0];   // N*1*H*W elements; mask has the same count

    bce_pass1<<<592, 512>>>(pred, gt, mask, n);
    bce_pass2<<<1, 1024>>>((float*)d_out);
}